// round 10
// baseline (speedup 1.0000x reference)
#include <cuda_runtime.h>

#define N_NODES 10000
#define N_EDGES 160000
#define NF      512
#define D1      128
#define D2      256

// Scratch layout (floats):
// [0,N)=y1  [N,2N)=y2  [2N,3N)=y3  [3N,4N)=s  [4N,5N)=t2
// then p[256], q[256], u[512], v[512], w[512]
#define OFF_Y1 0
#define OFF_Y2 (N_NODES)
#define OFF_Y3 (2 * N_NODES)
#define OFF_S  (3 * N_NODES)
#define OFF_T2 (4 * N_NODES)
#define OFF_P  (5 * N_NODES)
#define OFF_Q  (5 * N_NODES + 256)
#define OFF_U  (5 * N_NODES + 512)
#define OFF_V  (5 * N_NODES + 1024)
#define OFF_W  (5 * N_NODES + 1536)
#define SCRATCH_FLOATS (5 * N_NODES + 2048)

__device__ float g_scratch[SCRATCH_FLOATS];

// K0: zero node scratch + compute p = W1row@W2, q = b1@W2
__global__ void k0_init_pq(float* g,
                           const float* __restrict__ W1,
                           const float* __restrict__ b1,
                           const float* __restrict__ W2) {
    int t = blockIdx.x * blockDim.x + threadIdx.x;
    if (t < 5 * N_NODES) {
        g[t] = 0.0f;
        return;
    }
    int j2 = t - 5 * N_NODES;
    if (j2 < 2 * D2) {
        int j = j2 & (D2 - 1);
        const float* vec = (j2 < D2) ? W1 : b1;  // both length D1=128
        float acc = 0.0f;
        for (int k = 0; k < D1; k++)
            acc += vec[k] * W2[k * D2 + j];
        g[(j2 < D2 ? OFF_P : OFF_Q) + j] = acc;
    }
}

// K1: y1 = A x ; s = A 1    (edge_index: int32 [2, E] row-major)
__global__ void k1_spmv1(float* g,
                         const int* __restrict__ ei,
                         const float* __restrict__ ew,
                         const float* __restrict__ x) {
    int e = blockIdx.x * blockDim.x + threadIdx.x;
    if (e >= N_EDGES) return;
    int src = ei[e];
    int dst = ei[N_EDGES + e];
    if ((unsigned)src >= N_NODES || (unsigned)dst >= N_NODES) return;  // safety
    float w = ew[e];
    atomicAdd(g + OFF_Y1 + dst, w * x[src]);
    atomicAdd(g + OFF_S + dst, w);
}

// K2: y2 = A y1 ; t2 = A s ; plus u = p@W3, v = q@W3, w = b2@W3
__global__ void k2_spmv2_uvw(float* g,
                             const int* __restrict__ ei,
                             const float* __restrict__ ew,
                             const float* __restrict__ W3,
                             const float* __restrict__ b2) {
    int t = blockIdx.x * blockDim.x + threadIdx.x;
    if (t < N_EDGES) {
        int src = ei[t];
        int dst = ei[N_EDGES + t];
        if ((unsigned)src >= N_NODES || (unsigned)dst >= N_NODES) return;
        float w = ew[t];
        atomicAdd(g + OFF_Y2 + dst, w * g[OFF_Y1 + src]);
        atomicAdd(g + OFF_T2 + dst, w * g[OFF_S + src]);
        return;
    }
    int j3 = t - N_EDGES;
    if (j3 < 3 * NF) {
        int j = j3 & (NF - 1);
        int which = j3 >> 9;  // 0:u 1:v 2:w
        const float* vec = (which == 0) ? (g + OFF_P)
                         : (which == 1) ? (g + OFF_Q)
                                        : b2;
        float acc = 0.0f;
        for (int k = 0; k < D2; k++)
            acc += vec[k] * W3[k * NF + j];
        int dstoff = (which == 0) ? OFF_U : (which == 1) ? OFF_V : OFF_W;
        g[dstoff + j] = acc;
    }
}

// K3: y3 = A y2
__global__ void k3_spmv3(float* g,
                         const int* __restrict__ ei,
                         const float* __restrict__ ew) {
    int e = blockIdx.x * blockDim.x + threadIdx.x;
    if (e >= N_EDGES) return;
    int src = ei[e];
    int dst = ei[N_EDGES + e];
    if ((unsigned)src >= N_NODES || (unsigned)dst >= N_NODES) return;
    atomicAdd(g + OFF_Y3 + dst, ew[e] * g[OFF_Y2 + src]);
}

// K4: out[i,j] = sigmoid( y3[i]*u[j] + t2[i]*v[j] + s[i]*w[j] + b3[j] )
__global__ void __launch_bounds__(128) k4_out(const float* __restrict__ g,
                                              const float* __restrict__ b3,
                                              float* __restrict__ out) {
    int i = blockIdx.x;
    int j = threadIdx.x * 4;
    float a = g[OFF_Y3 + i];
    float b = g[OFF_T2 + i];
    float c = g[OFF_S + i];
    float4 o;
    float z;
    z = fmaf(a, g[OFF_U + j + 0], fmaf(b, g[OFF_V + j + 0], fmaf(c, g[OFF_W + j + 0], b3[j + 0])));
    o.x = 1.0f / (1.0f + __expf(-z));
    z = fmaf(a, g[OFF_U + j + 1], fmaf(b, g[OFF_V + j + 1], fmaf(c, g[OFF_W + j + 1], b3[j + 1])));
    o.y = 1.0f / (1.0f + __expf(-z));
    z = fmaf(a, g[OFF_U + j + 2], fmaf(b, g[OFF_V + j + 2], fmaf(c, g[OFF_W + j + 2], b3[j + 2])));
    o.z = 1.0f / (1.0f + __expf(-z));
    z = fmaf(a, g[OFF_U + j + 3], fmaf(b, g[OFF_V + j + 3], fmaf(c, g[OFF_W + j + 3], b3[j + 3])));
    o.w = 1.0f / (1.0f + __expf(-z));
    *reinterpret_cast<float4*>(out + (size_t)i * NF + j) = o;
}

extern "C" void kernel_launch(void* const* d_in, const int* in_sizes, int n_in,
                              void* d_out, int out_size) {
    const float* x  = (const float*)d_in[0];
    const int*   ei = (const int*)d_in[1];   // int32 [2, E]: row0=src, row1=dst
    const float* ew = (const float*)d_in[2];
    const float* W1 = (const float*)d_in[3];
    const float* b1 = (const float*)d_in[4];
    const float* W2 = (const float*)d_in[5];
    const float* b2 = (const float*)d_in[6];
    const float* W3 = (const float*)d_in[7];
    const float* b3 = (const float*)d_in[8];
    float* out = (float*)d_out;

    float* g = nullptr;
    cudaGetSymbolAddress((void**)&g, g_scratch);  // host-side query; capture-safe

    const int BS = 256;
    int k0_jobs = 5 * N_NODES + 2 * D2;
    k0_init_pq<<<(k0_jobs + BS - 1) / BS, BS>>>(g, W1, b1, W2);

    k1_spmv1<<<(N_EDGES + BS - 1) / BS, BS>>>(g, ei, ew, x);

    int k2_jobs = N_EDGES + 3 * NF;
    k2_spmv2_uvw<<<(k2_jobs + BS - 1) / BS, BS>>>(g, ei, ew, W3, b2);

    k3_spmv3<<<(N_EDGES + BS - 1) / BS, BS>>>(g, ei, ew);

    k4_out<<<N_NODES, 128>>>(g, b3, out);
}

// round 11
// speedup vs baseline: 1.0494x; 1.0494x over previous
#include <cuda_runtime.h>

#define N_NODES 10000
#define N_EDGES 160000
#define NF      512
#define D1      128
#define D2      256

#define NBLK 592            // 4 CTAs/SM * 148 SMs -> guaranteed single wave
#define NTHR 256
#define TOTTHR (NBLK * NTHR)  // 151,552 threads

// Scratch layout (floats):
// [0,N)=y1  [N,2N)=y2  [2N,3N)=y3  [3N,4N)=s  [4N,5N)=t2
// then p[256], q[256], u[512], v[512], w[512]
#define OFF_Y1 0
#define OFF_Y2 (N_NODES)
#define OFF_Y3 (2 * N_NODES)
#define OFF_S  (3 * N_NODES)
#define OFF_T2 (4 * N_NODES)
#define OFF_P  (5 * N_NODES)
#define OFF_Q  (5 * N_NODES + 256)
#define OFF_U  (5 * N_NODES + 512)
#define OFF_V  (5 * N_NODES + 1024)
#define OFF_W  (5 * N_NODES + 1536)
#define SCRATCH_FLOATS (5 * N_NODES + 2048)

__device__ float    g_scratch[SCRATCH_FLOATS];
__device__ unsigned g_ctr[8];   // monotonic epoch counters (never reset)

// Single-wave grid barrier: monotonic epochs, wrap-safe, replay-safe.
__device__ __forceinline__ void gsync(int p) {
    __threadfence();          // release: make this thread's writes visible
    __syncthreads();
    if (threadIdx.x == 0) {
        unsigned old = atomicAdd(&g_ctr[p], 1u);
        unsigned target = old - (old % NBLK) + NBLK;
        while ((int)(*(volatile unsigned*)&g_ctr[p] - target) < 0)
            __nanosleep(64);
        __threadfence();      // acquire
    }
    __syncthreads();
}

__device__ __forceinline__ float sigf(float z) {
    float h = 0.5f * z, t;
    asm("tanh.approx.f32 %0, %1;" : "=f"(t) : "f"(h));
    return fmaf(0.5f, t, 0.5f);
}

__global__ void __launch_bounds__(NTHR, 4)
fused_gcn(float* __restrict__ g,
          const float* __restrict__ x,
          const int*   __restrict__ ei,   // int32 [2,E]: row0=src, row1=dst
          const float* __restrict__ ew,
          const float* __restrict__ W1,
          const float* __restrict__ b1,
          const float* __restrict__ W2,
          const float* __restrict__ b2,
          const float* __restrict__ W3,
          const float* __restrict__ b3,
          float* __restrict__ out) {
    const int tid = blockIdx.x * NTHR + threadIdx.x;

    // ---------- Phase A: zero node scratch; p = W1row@W2, q = b1@W2 ----------
    if (tid < 5 * N_NODES) {
        g[tid] = 0.0f;
    } else {
        int j2 = tid - 5 * N_NODES;
        if (j2 < 2 * D2) {
            int j = j2 & (D2 - 1);
            const float* vec = (j2 < D2) ? W1 : b1;   // both length D1=128
            float acc = 0.0f;
            #pragma unroll 8
            for (int k = 0; k < D1; k++)
                acc += vec[k] * W2[k * D2 + j];
            g[(j2 < D2 ? OFF_P : OFF_Q) + j] = acc;
        }
    }
    gsync(0);

    // ---------- Phase B: y1 = A x ; s = A 1 ; u,v,w dot-chains ----------
    for (int e = tid; e < N_EDGES; e += TOTTHR) {
        int src = ei[e];
        int dst = ei[N_EDGES + e];
        if ((unsigned)src < N_NODES && (unsigned)dst < N_NODES) {
            float w = ew[e];
            atomicAdd(g + OFF_Y1 + dst, w * x[src]);
            atomicAdd(g + OFF_S + dst, w);
        }
    }
    {
        int j3 = tid - (TOTTHR - 3 * NF);     // last 1536 threads also do dots
        if (j3 >= 0) {
            int j = j3 & (NF - 1);
            int which = j3 >> 9;              // 0:u 1:v 2:w
            const float* vec = (which == 0) ? (g + OFF_P)
                             : (which == 1) ? (g + OFF_Q)
                                            : b2;
            float acc = 0.0f;
            #pragma unroll 8
            for (int k = 0; k < D2; k++)
                acc += vec[k] * W3[k * NF + j];
            int dstoff = (which == 0) ? OFF_U : (which == 1) ? OFF_V : OFF_W;
            g[dstoff + j] = acc;
        }
    }
    gsync(1);

    // ---------- Phase C: y2 = A y1 ; t2 = A s ----------
    for (int e = tid; e < N_EDGES; e += TOTTHR) {
        int src = ei[e];
        int dst = ei[N_EDGES + e];
        if ((unsigned)src < N_NODES && (unsigned)dst < N_NODES) {
            float w = ew[e];
            float a = g[OFF_Y1 + src];
            float bsv = g[OFF_S + src];
            atomicAdd(g + OFF_Y2 + dst, w * a);
            atomicAdd(g + OFF_T2 + dst, w * bsv);
        }
    }
    gsync(2);

    // ---------- Phase D: y3 = A y2 ----------
    for (int e = tid; e < N_EDGES; e += TOTTHR) {
        int src = ei[e];
        int dst = ei[N_EDGES + e];
        if ((unsigned)src < N_NODES && (unsigned)dst < N_NODES)
            atomicAdd(g + OFF_Y3 + dst, ew[e] * g[OFF_Y2 + src]);
    }
    gsync(3);

    // ---------- Phase E: out[i,j] = sigmoid(y3*u + t2*v + s*w + b3) ----------
    __shared__ float4 su[NF / 4], sv[NF / 4], sw[NF / 4], sb[NF / 4];
    for (int j = threadIdx.x; j < NF / 4; j += NTHR) {
        su[j] = *reinterpret_cast<const float4*>(g + OFF_U + 4 * j);
        sv[j] = *reinterpret_cast<const float4*>(g + OFF_V + 4 * j);
        sw[j] = *reinterpret_cast<const float4*>(g + OFF_W + 4 * j);
        sb[j] = *reinterpret_cast<const float4*>(b3 + 4 * j);
    }
    __syncthreads();

    const int TOT4 = N_NODES * (NF / 4);      // 1,280,000 float4 elements
    for (int idx = tid; idx < TOT4; idx += TOTTHR) {
        int i  = idx >> 7;                    // node (128 float4 per node)
        int jv = idx & 127;
        float a = g[OFF_Y3 + i];
        float b = g[OFF_T2 + i];
        float c = g[OFF_S + i];
        float4 u4 = su[jv], v4 = sv[jv], w4 = sw[jv], b4 = sb[jv];
        float4 o;
        o.x = sigf(fmaf(a, u4.x, fmaf(b, v4.x, fmaf(c, w4.x, b4.x))));
        o.y = sigf(fmaf(a, u4.y, fmaf(b, v4.y, fmaf(c, w4.y, b4.y))));
        o.z = sigf(fmaf(a, u4.z, fmaf(b, v4.z, fmaf(c, w4.z, b4.z))));
        o.w = sigf(fmaf(a, u4.w, fmaf(b, v4.w, fmaf(c, w4.w, b4.w))));
        *reinterpret_cast<float4*>(out + (size_t)idx * 4) = o;
    }
}

extern "C" void kernel_launch(void* const* d_in, const int* in_sizes, int n_in,
                              void* d_out, int out_size) {
    const float* x  = (const float*)d_in[0];
    const int*   ei = (const int*)d_in[1];
    const float* ew = (const float*)d_in[2];
    const float* W1 = (const float*)d_in[3];
    const float* b1 = (const float*)d_in[4];
    const float* W2 = (const float*)d_in[5];
    const float* b2 = (const float*)d_in[6];
    const float* W3 = (const float*)d_in[7];
    const float* b3 = (const float*)d_in[8];
    float* out = (float*)d_out;

    float* g = nullptr;
    cudaGetSymbolAddress((void**)&g, g_scratch);

    fused_gcn<<<NBLK, NTHR>>>(g, x, ei, ew, W1, b1, W2, b2, W3, b3, out);
}

// round 14
// speedup vs baseline: 1.2980x; 1.2369x over previous
#include <cuda_runtime.h>

#define N_NODES 10000
#define N_EDGES 160000
#define NF      512
#define D1      128
#define D2      256

#define NBLK 592              // 4 CTAs/SM * 148 SMs -> single wave
#define NTHR 256
#define TOTTHR (NBLK * NTHR)  // 151,552 threads
#define NODE_SLOTS (TOTTHR / 128)  // 1184 node groups in epilogue

// Scratch layout (floats):
// [0,N)=y1 [N,2N)=y2 [2N,3N)=y3 [3N,4N)=s [4N,5N)=t2, then p[256] q[256] u[512] v[512] w[512]
#define OFF_Y1 0
#define OFF_Y2 (N_NODES)
#define OFF_Y3 (2 * N_NODES)
#define OFF_S  (3 * N_NODES)
#define OFF_T2 (4 * N_NODES)
#define OFF_P  (5 * N_NODES)
#define OFF_Q  (5 * N_NODES + 256)
#define OFF_U  (5 * N_NODES + 512)
#define OFF_V  (5 * N_NODES + 1024)
#define OFF_W  (5 * N_NODES + 1536)
#define SCRATCH_FLOATS (5 * N_NODES + 2048)

__device__ float    g_scratch[SCRATCH_FLOATS];
__device__ unsigned g_ctr[8];   // monotonic epoch counters (replay-safe)

// Single-wave grid barrier: monotonic epochs, wrap-safe.
__device__ __forceinline__ void gsync(int p) {
    __threadfence();
    __syncthreads();
    if (threadIdx.x == 0) {
        unsigned old = atomicAdd(&g_ctr[p], 1u);
        unsigned target = old - (old % NBLK) + NBLK;
        while ((int)(*(volatile unsigned*)&g_ctr[p] - target) < 0)
            __nanosleep(32);
        __threadfence();
    }
    __syncthreads();
}

__device__ __forceinline__ float sigf(float z) {
    float t;
    asm("tanh.approx.f32 %0, %1;" : "=f"(t) : "f"(0.5f * z));
    return fmaf(0.5f, t, 0.5f);
}

__global__ void __launch_bounds__(NTHR, 4)
fused_gcn(float* __restrict__ g,
          const float* __restrict__ x,
          const int*   __restrict__ ei,   // int32 [2,E]: row0=src, row1=dst
          const float* __restrict__ ew,
          const float* __restrict__ W1,
          const float* __restrict__ b1,
          const float* __restrict__ W2,
          const float* __restrict__ b2,
          const float* __restrict__ W3,
          const float* __restrict__ b3,
          float* __restrict__ out) {
    const int tid   = blockIdx.x * NTHR + threadIdx.x;
    const int gwarp = tid >> 5;
    const int lane  = tid & 31;

    // ---- Prologue: zero scratch, and prefetch this thread's edge(s) ----
    if (tid < SCRATCH_FLOATS) g[tid] = 0.0f;

    // Edge 0 (tid < N_EDGES always, since TOTTHR < N_EDGES)
    int   src0 = ei[tid];
    int   dst0 = ei[N_EDGES + tid];
    float w0   = ew[tid];
    bool  ok0  = ((unsigned)src0 < N_NODES) & ((unsigned)dst0 < N_NODES);
    float xv0  = ok0 ? x[src0] : 0.0f;

    // Edge 1 (only tid < N_EDGES - TOTTHR = 8448)
    const int e1 = tid + TOTTHR;
    bool  ok1 = false;
    int   src1 = 0, dst1 = 0;
    float w1 = 0.0f, xv1 = 0.0f;
    if (e1 < N_EDGES) {
        src1 = ei[e1];
        dst1 = ei[N_EDGES + e1];
        w1   = ew[e1];
        ok1  = ((unsigned)src1 < N_NODES) & ((unsigned)dst1 < N_NODES);
        if (ok1) xv1 = x[src1];
    }
    gsync(0);

    // ---- Phase 1: y1 = A x ; s = A 1 ; p = W1@W2, q = b1@W2 (split-K) ----
    if (ok0) {
        atomicAdd(g + OFF_Y1 + dst0, w0 * xv0);
        atomicAdd(g + OFF_S + dst0, w0);
    }
    if (ok1) {
        atomicAdd(g + OFF_Y1 + dst1, w1 * xv1);
        atomicAdd(g + OFF_S + dst1, w1);
    }
    if (gwarp < 128) {                      // 2 vec x 8 jb x 8 kc
        int kc  = gwarp & 7;
        int jb  = (gwarp >> 3) & 7;
        int vec = gwarp >> 6;
        const float* vs = vec ? b1 : W1;    // both length 128
        int j = jb * 32 + lane;
        float acc = 0.0f;
        #pragma unroll
        for (int kk = 0; kk < 16; kk++) {
            int k = kc * 16 + kk;
            acc = fmaf(vs[k], W2[k * D2 + j], acc);
        }
        atomicAdd(g + (vec ? OFF_Q : OFF_P) + j, acc);
    }
    gsync(1);

    // ---- Phase 2: y2 = A y1 ; t2 = A s ; u,v,w = (p,q,b2)@W3 (split-K) ----
    if (ok0) {
        atomicAdd(g + OFF_Y2 + dst0, w0 * g[OFF_Y1 + src0]);
        atomicAdd(g + OFF_T2 + dst0, w0 * g[OFF_S + src0]);
    }
    if (ok1) {
        atomicAdd(g + OFF_Y2 + dst1, w1 * g[OFF_Y1 + src1]);
        atomicAdd(g + OFF_T2 + dst1, w1 * g[OFF_S + src1]);
    }
    if (gwarp < 768) {                      // 3 vec x 16 jb x 16 kc
        int kc  = gwarp & 15;
        int jb  = (gwarp >> 4) & 15;
        int vec = gwarp >> 8;
        const float* vs = (vec == 0) ? (g + OFF_P)
                        : (vec == 1) ? (g + OFF_Q) : b2;
        int j = jb * 32 + lane;
        float acc = 0.0f;
        #pragma unroll
        for (int kk = 0; kk < 16; kk++) {
            int k = kc * 16 + kk;
            acc = fmaf(vs[k], W3[k * NF + j], acc);
        }
        int dstoff = (vec == 0) ? OFF_U : (vec == 1) ? OFF_V : OFF_W;
        atomicAdd(g + dstoff + j, acc);
    }
    gsync(2);

    // ---- Phase 3: y3 = A y2 ----
    if (ok0) atomicAdd(g + OFF_Y3 + dst0, w0 * g[OFF_Y2 + src0]);
    if (ok1) atomicAdd(g + OFF_Y3 + dst1, w1 * g[OFF_Y2 + src1]);
    gsync(3);

    // ---- Phase 4: out[i,j] = sigmoid(y3*u + t2*v + s*w + b3) ----
    // Fixed column group per thread; u/v/w/b3 live in registers.
    {
        const int col4 = tid & 127;         // which float4 of the 128 per node
        const int jj = col4 * 4;
        float4 u4 = *reinterpret_cast<const float4*>(g + OFF_U + jj);
        float4 v4 = *reinterpret_cast<const float4*>(g + OFF_V + jj);
        float4 w4 = *reinterpret_cast<const float4*>(g + OFF_W + jj);
        float4 b4 = *reinterpret_cast<const float4*>(b3 + jj);

        int i = tid >> 7;                   // 0..1183, warp-uniform
        float a = g[OFF_Y3 + i];
        float b = g[OFF_T2 + i];
        float c = g[OFF_S + i];
        while (i < N_NODES) {
            int inext = i + NODE_SLOTS;
            float an = 0.f, bn = 0.f, cn = 0.f;
            if (inext < N_NODES) {          // prefetch next node's scalars
                an = g[OFF_Y3 + inext];
                bn = g[OFF_T2 + inext];
                cn = g[OFF_S + inext];
            }
            float4 o;
            o.x = sigf(fmaf(a, u4.x, fmaf(b, v4.x, fmaf(c, w4.x, b4.x))));
            o.y = sigf(fmaf(a, u4.y, fmaf(b, v4.y, fmaf(c, w4.y, b4.y))));
            o.z = sigf(fmaf(a, u4.z, fmaf(b, v4.z, fmaf(c, w4.z, b4.z))));
            o.w = sigf(fmaf(a, u4.w, fmaf(b, v4.w, fmaf(c, w4.w, b4.w))));
            *reinterpret_cast<float4*>(out + (size_t)i * NF + jj) = o;
            i = inext; a = an; b = bn; c = cn;
        }
    }
}

extern "C" void kernel_launch(void* const* d_in, const int* in_sizes, int n_in,
                              void* d_out, int out_size) {
    const float* x  = (const float*)d_in[0];
    const int*   ei = (const int*)d_in[1];
    const float* ew = (const float*)d_in[2];
    const float* W1 = (const float*)d_in[3];
    const float* b1 = (const float*)d_in[4];
    const float* W2 = (const float*)d_in[5];
    const float* b2 = (const float*)d_in[6];
    const float* W3 = (const float*)d_in[7];
    const float* b3 = (const float*)d_in[8];
    float* out = (float*)d_out;

    float* g = nullptr;
    cudaGetSymbolAddress((void**)&g, g_scratch);

    fused_gcn<<<NBLK, NTHR>>>(g, x, ei, ew, W1, b1, W2, b2, W3, b3, out);
}

// round 17
// speedup vs baseline: 1.4112x; 1.0872x over previous
#include <cuda_runtime.h>

#define N_NODES 10000
#define N_EDGES 160000
#define NF      512
#define D1      128
#define D2      256

#define NBLK 148              // 1 CTA/SM -> single wave, 148 barrier arrivals
#define NTHR 1024
#define TOTTHR (NBLK * NTHR)  // 151,552 threads
#define NODE_SLOTS (TOTTHR / 128)  // 1184 node groups in epilogue

// Scratch layout (floats):
// [0,2N)   g12 = float2 {y1, s} per node
// [2N,4N)  g34 = float2 {y2, t2} per node
// [4N,5N)  y3
// [5N, +256)=p  [+256,+512)=q  then u[512] v[512] w[512]
#define OFF_G12 0
#define OFF_G34 (2 * N_NODES)
#define OFF_Y3  (4 * N_NODES)
#define OFF_P   (5 * N_NODES)
#define OFF_Q   (5 * N_NODES + 256)
#define OFF_U   (5 * N_NODES + 512)
#define OFF_V   (5 * N_NODES + 1024)
#define OFF_W   (5 * N_NODES + 1536)
#define SCRATCH_FLOATS (5 * N_NODES + 2048)

__device__ __align__(16) float    g_scratch[SCRATCH_FLOATS];
__device__ unsigned g_ctr[8];   // monotonic epoch counters (replay-safe)

// Single-wave grid barrier: monotonic epochs, wrap-safe.
__device__ __forceinline__ void gsync(int p) {
    __threadfence();
    __syncthreads();
    if (threadIdx.x == 0) {
        unsigned old = atomicAdd(&g_ctr[p], 1u);
        unsigned target = old - (old % NBLK) + NBLK;
        while ((int)(*(volatile unsigned*)&g_ctr[p] - target) < 0)
            __nanosleep(32);
        __threadfence();
    }
    __syncthreads();
}

__device__ __forceinline__ float sigf(float z) {
    float t;
    asm("tanh.approx.f32 %0, %1;" : "=f"(t) : "f"(0.5f * z));
    return fmaf(0.5f, t, 0.5f);
}

__global__ void __launch_bounds__(NTHR, 1)
fused_gcn(float* __restrict__ g,
          const float* __restrict__ x,
          const int*   __restrict__ ei,   // int32 [2,E]: row0=src, row1=dst
          const float* __restrict__ ew,
          const float* __restrict__ W1,
          const float* __restrict__ b1,
          const float* __restrict__ W2,
          const float* __restrict__ b2,
          const float* __restrict__ W3,
          const float* __restrict__ b3,
          float* __restrict__ out) {
    const int tid   = blockIdx.x * NTHR + threadIdx.x;
    const int gwarp = tid >> 5;
    const int lane  = tid & 31;
    const float4 z4 = make_float4(0.f, 0.f, 0.f, 0.f);

    // ---- Prologue: zero ONLY phase-1 outputs (g12, p, q); prefetch edges ----
    if (tid < 5000) {                                   // g12: 2N floats
        *reinterpret_cast<float4*>(g + OFF_G12 + 4 * tid) = z4;
    } else if (tid < 5128) {                            // p,q: 512 floats
        *reinterpret_cast<float4*>(g + OFF_P + 4 * (tid - 5000)) = z4;
    }

    int   src0 = ei[tid];
    int   dst0 = ei[N_EDGES + tid];
    float w0   = ew[tid];
    bool  ok0  = ((unsigned)src0 < N_NODES) & ((unsigned)dst0 < N_NODES);
    float xv0  = ok0 ? x[src0] : 0.0f;

    const int e1 = tid + TOTTHR;                        // tid < 8448 only
    bool  ok1 = false;
    int   src1 = 0, dst1 = 0;
    float w1 = 0.0f, xv1 = 0.0f;
    if (e1 < N_EDGES) {
        src1 = ei[e1];
        dst1 = ei[N_EDGES + e1];
        w1   = ew[e1];
        ok1  = ((unsigned)src1 < N_NODES) & ((unsigned)dst1 < N_NODES);
        if (ok1) xv1 = x[src1];
    }
    gsync(0);

    // ---- Phase 1: scatter {y1,s}; p,q split-K dots; zero phase-2/3 outputs ----
    if (ok0) {
        atomicAdd(g + OFF_G12 + 2 * dst0,     w0 * xv0);  // y1
        atomicAdd(g + OFF_G12 + 2 * dst0 + 1, w0);        // s
    }
    if (ok1) {
        atomicAdd(g + OFF_G12 + 2 * dst1,     w1 * xv1);
        atomicAdd(g + OFF_G12 + 2 * dst1 + 1, w1);
    }
    if (gwarp < 128) {                      // p,q: 2 vec x 8 jb x 8 kc
        int kc  = gwarp & 7;
        int jb  = (gwarp >> 3) & 7;
        int vec = gwarp >> 6;
        const float* vs = vec ? b1 : W1;    // both length 128
        int j = jb * 32 + lane;
        float acc = 0.0f;
        #pragma unroll
        for (int kk = 0; kk < 16; kk++) {
            int k = kc * 16 + kk;
            acc = fmaf(vs[k], W2[k * D2 + j], acc);
        }
        atomicAdd(g + (vec ? OFF_Q : OFF_P) + j, acc);
    }
    // zero g34 (5000 f4), y3 (2500 f4), u/v/w (384 f4)
    if (tid < 5000) {
        *reinterpret_cast<float4*>(g + OFF_G34 + 4 * tid) = z4;
    } else if (tid < 7500) {
        *reinterpret_cast<float4*>(g + OFF_Y3 + 4 * (tid - 5000)) = z4;
    } else if (tid < 7884) {
        *reinterpret_cast<float4*>(g + OFF_U + 4 * (tid - 7500)) = z4;
    }
    gsync(1);

    // ---- Phase 2: scatter {y2,t2}; u,v,w split-K dots ----
    if (ok0) {
        float2 a = *reinterpret_cast<const float2*>(g + OFF_G12 + 2 * src0);
        atomicAdd(g + OFF_G34 + 2 * dst0,     w0 * a.x);  // y2
        atomicAdd(g + OFF_G34 + 2 * dst0 + 1, w0 * a.y);  // t2
    }
    if (ok1) {
        float2 a = *reinterpret_cast<const float2*>(g + OFF_G12 + 2 * src1);
        atomicAdd(g + OFF_G34 + 2 * dst1,     w1 * a.x);
        atomicAdd(g + OFF_G34 + 2 * dst1 + 1, w1 * a.y);
    }
    if (gwarp < 768) {                      // u,v,w: 3 vec x 16 jb x 16 kc
        int kc  = gwarp & 15;
        int jb  = (gwarp >> 4) & 15;
        int vec = gwarp >> 8;
        const float* vs = (vec == 0) ? (g + OFF_P)
                        : (vec == 1) ? (g + OFF_Q) : b2;
        int j = jb * 32 + lane;
        float acc = 0.0f;
        #pragma unroll
        for (int kk = 0; kk < 16; kk++) {
            int k = kc * 16 + kk;
            acc = fmaf(vs[k], W3[k * NF + j], acc);
        }
        int dstoff = (vec == 0) ? OFF_U : (vec == 1) ? OFF_V : OFF_W;
        atomicAdd(g + dstoff + j, acc);
    }
    gsync(2);

    // ---- Phase 3: y3 scatter; overlap epilogue coefficient prefetch ----
    const int jj = (tid & 127) * 4;         // this thread's fixed column group
    float4 u4 = *reinterpret_cast<const float4*>(g + OFF_U + jj);
    float4 v4 = *reinterpret_cast<const float4*>(g + OFF_V + jj);
    float4 w4 = *reinterpret_cast<const float4*>(g + OFF_W + jj);
    float4 b4 = *reinterpret_cast<const float4*>(b3 + jj);

    if (ok0) atomicAdd(g + OFF_Y3 + dst0, w0 * g[OFF_G34 + 2 * src0]);
    if (ok1) atomicAdd(g + OFF_Y3 + dst1, w1 * g[OFF_G34 + 2 * src1]);
    gsync(3);

    // ---- Phase 4: out[i,j] = sigmoid(y3*u + t2*v + s*w + b3) ----
    {
        int i = tid >> 7;                   // 0..1183, warp-uniform
        float a = g[OFF_Y3 + i];
        float b = g[OFF_G34 + 2 * i + 1];   // t2
        float c = g[OFF_G12 + 2 * i + 1];   // s
        while (i < N_NODES) {
            int inext = i + NODE_SLOTS;
            float an = 0.f, bn = 0.f, cn = 0.f;
            if (inext < N_NODES) {          // prefetch next node's scalars
                an = g[OFF_Y3 + inext];
                bn = g[OFF_G34 + 2 * inext + 1];
                cn = g[OFF_G12 + 2 * inext + 1];
            }
            float4 o;
            o.x = sigf(fmaf(a, u4.x, fmaf(b, v4.x, fmaf(c, w4.x, b4.x))));
            o.y = sigf(fmaf(a, u4.y, fmaf(b, v4.y, fmaf(c, w4.y, b4.y))));
            o.z = sigf(fmaf(a, u4.z, fmaf(b, v4.z, fmaf(c, w4.z, b4.z))));
            o.w = sigf(fmaf(a, u4.w, fmaf(b, v4.w, fmaf(c, w4.w, b4.w))));
            *reinterpret_cast<float4*>(out + (size_t)i * NF + jj) = o;
            i = inext; a = an; b = bn; c = cn;
        }
    }
}

extern "C" void kernel_launch(void* const* d_in, const int* in_sizes, int n_in,
                              void* d_out, int out_size) {
    const float* x  = (const float*)d_in[0];
    const int*   ei = (const int*)d_in[1];
    const float* ew = (const float*)d_in[2];
    const float* W1 = (const float*)d_in[3];
    const float* b1 = (const float*)d_in[4];
    const float* W2 = (const float*)d_in[5];
    const float* b2 = (const float*)d_in[6];
    const float* W3 = (const float*)d_in[7];
    const float* b3 = (const float*)d_in[8];
    float* out = (float*)d_out;

    float* g = nullptr;
    cudaGetSymbolAddress((void**)&g, g_scratch);

    fused_gcn<<<NBLK, NTHR>>>(g, x, ei, ew, W1, b1, W2, b2, W3, b3, out);
}